// round 1
// baseline (speedup 1.0000x reference)
#include <cuda_runtime.h>
#include <cstddef>

#define BSZ  1024
#define HD   1024
#define VOUT 50000
#define VINP 32000
#define SRCN 256

// ---------------- scratch (static device globals; no runtime allocation) ----
__device__ float g_W2[(size_t)VOUT * HD];   // permuted weights: W2[j,:] = W[out_map[j],:]
__device__ float g_b2[VOUT];                // permuted bias
__device__ float g_G [(size_t)BSZ * VOUT];  // gen_scores, later out_scores (in-place scatter)
__device__ int   g_sel[VOUT];
__device__ int   g_win[VINP];
__device__ float g_rowmax[BSZ];
__device__ float g_rowinv[BSZ];

// ---------------- small prep kernels ----------------------------------------
__global__ void k_sel_init() {
    int i = blockIdx.x * 256 + threadIdx.x;
    if (i < VOUT) g_sel[i] = -1;
}

__global__ void k_sel_max(const int* __restrict__ i2a) {
    int i = blockIdx.x * 256 + threadIdx.x;
    if (i < VINP) atomicMax(&g_sel[i2a[i]], i);
}

__global__ void k_win_build(const int* __restrict__ i2a) {
    int i = blockIdx.x * 256 + threadIdx.x;
    if (i < VINP) {
        int a = i2a[i];
        g_win[i] = (g_sel[a] == i) ? a : -1;
    }
}

// W2[j,:] = W[out_map[j],:]; b2[j] = b[out_map[j]].  One block per output row.
__global__ void k_perm_w(const float* __restrict__ W, const float* __restrict__ bias,
                         const int* __restrict__ omap) {
    int j  = blockIdx.x;
    int om = omap[j];
    const float4* src = (const float4*)(W + (size_t)om * HD);
    float4*       dst = (float4*)(g_W2 + (size_t)j * HD);
    dst[threadIdx.x] = src[threadIdx.x];           // 256 threads * 4 = 1024 floats
    if (threadIdx.x == 0) g_b2[j] = bias[om];
}

// ---------------- GEMM: G[m,n] = sum_k x[m,k]*W2[n,k] + b2[n] ---------------
// 128x128x16 tiles, 256 threads, 8x8 per-thread micro-tile, 2-stage pipeline.
__global__ __launch_bounds__(256, 2)
void k_gemm(const float* __restrict__ A) {
    __shared__ float As[2][16][132];
    __shared__ float Bs[2][16][132];

    const int tid = threadIdx.x;
    const int tx  = tid & 15;        // 0..15  -> n micro
    const int ty  = tid >> 4;        // 0..15  -> m micro
    const int m0  = blockIdx.y * 128;
    const int n0  = blockIdx.x * 128;

    float acc[8][8];
#pragma unroll
    for (int i = 0; i < 8; ++i)
#pragma unroll
        for (int j = 0; j < 8; ++j) acc[i][j] = 0.f;

    float4 Ar[2], Br[2];

    // ---- load tile (kb) into registers
#define LOAD_TILE(kb)                                                          \
    {                                                                          \
        _Pragma("unroll")                                                      \
        for (int s = 0; s < 2; ++s) {                                          \
            int l = tid + s * 256;                                             \
            int r = l >> 2, c = l & 3;                                         \
            Ar[s] = *(const float4*)(A + (size_t)(m0 + r) * HD + (kb) + c * 4);\
            int nn = n0 + r;                                                   \
            if (nn < VOUT)                                                     \
                Br[s] = *(const float4*)(g_W2 + (size_t)nn * HD + (kb) + c*4); \
            else                                                               \
                Br[s] = make_float4(0.f, 0.f, 0.f, 0.f);                       \
        }                                                                      \
    }

    // ---- store registers into smem buffer buf (transposed to [k][m]/[k][n])
#define STORE_TILE(buf)                                                        \
    {                                                                          \
        _Pragma("unroll")                                                      \
        for (int s = 0; s < 2; ++s) {                                          \
            int l = tid + s * 256;                                             \
            int r = l >> 2, c = l & 3;                                         \
            As[buf][c * 4 + 0][r] = Ar[s].x;                                   \
            As[buf][c * 4 + 1][r] = Ar[s].y;                                   \
            As[buf][c * 4 + 2][r] = Ar[s].z;                                   \
            As[buf][c * 4 + 3][r] = Ar[s].w;                                   \
            Bs[buf][c * 4 + 0][r] = Br[s].x;                                   \
            Bs[buf][c * 4 + 1][r] = Br[s].y;                                   \
            Bs[buf][c * 4 + 2][r] = Br[s].z;                                   \
            Bs[buf][c * 4 + 3][r] = Br[s].w;                                   \
        }                                                                      \
    }

    LOAD_TILE(0);
    STORE_TILE(0);
    __syncthreads();

    int buf = 0;
    const int NT = HD / 16;   // 64
    for (int t = 0; t < NT; ++t) {
        if (t + 1 < NT) LOAD_TILE((t + 1) * 16);

#pragma unroll
        for (int k = 0; k < 16; ++k) {
            float a[8], bv[8];
            *(float4*)&a[0]  = *(const float4*)&As[buf][k][ty * 8];
            *(float4*)&a[4]  = *(const float4*)&As[buf][k][ty * 8 + 4];
            *(float4*)&bv[0] = *(const float4*)&Bs[buf][k][tx * 8];
            *(float4*)&bv[4] = *(const float4*)&Bs[buf][k][tx * 8 + 4];
#pragma unroll
            for (int i = 0; i < 8; ++i)
#pragma unroll
                for (int j = 0; j < 8; ++j)
                    acc[i][j] += a[i] * bv[j];
        }

        if (t + 1 < NT) {
            STORE_TILE(buf ^ 1);
            __syncthreads();
            buf ^= 1;
        }
    }

    // epilogue: add bias, store (guard N edge: last tile is 80 wide)
    float bias[8];
#pragma unroll
    for (int j = 0; j < 8; ++j) {
        int n = n0 + tx * 8 + j;
        bias[j] = (n < VOUT) ? g_b2[n] : 0.f;
    }
#pragma unroll
    for (int i = 0; i < 8; ++i) {
        int m = m0 + ty * 8 + i;
        float* Cp = g_G + (size_t)m * VOUT;
#pragma unroll
        for (int j = 0; j < 8; ++j) {
            int n = n0 + tx * 8 + j;
            if (n < VOUT) Cp[n] = acc[i][j] + bias[j];
        }
    }
#undef LOAD_TILE
#undef STORE_TILE
}

// ---------------- gen_masked = G - 1e6*mask  (reads gen BEFORE scatter) -----
__global__ void k_masked(const int* __restrict__ mask, float* __restrict__ out2) {
    int b  = blockIdx.y;
    int i4 = blockIdx.x * blockDim.x + threadIdx.x;
    if (i4 < VOUT / 4) {
        float4 g  = *((const float4*)(g_G + (size_t)b * VOUT) + i4);
        int4   mk = *((const int4*)(mask + (size_t)b * VOUT) + i4);
        float4 o;
        o.x = g.x - 1.0e6f * (float)mk.x;
        o.y = g.y - 1.0e6f * (float)mk.y;
        o.z = g.z - 1.0e6f * (float)mk.z;
        o.w = g.w - 1.0e6f * (float)mk.w;
        *((float4*)(out2 + (size_t)b * VOUT) + i4) = o;
    }
}

// ---------------- scatter pointer scores into G (G becomes out_scores) ------
__global__ void k_scatter(const float* __restrict__ attn, const int* __restrict__ ctx) {
    int b = blockIdx.x;
    int j = threadIdx.x;
    int v = ctx[b * SRCN + j];
    int o = g_win[v];
    if (o >= 0) atomicAdd(g_G + (size_t)b * VOUT + o, attn[b * SRCN + j]);
}

// ---------------- online softmax reduce: per-row (max, sumexp) --------------
__global__ void k_reduce() {
    int b = blockIdx.x;
    const float4* Gr = (const float4*)(g_G + (size_t)b * VOUT);
    float m = -3.4e38f, s = 0.f;
    for (int i = threadIdx.x; i < VOUT / 4; i += blockDim.x) {
        float4 v = Gr[i];
#define ONL(x)                                             \
        if ((x) > m) { s = s * __expf(m - (x)) + 1.f; m = (x); } \
        else         { s += __expf((x) - m); }
        ONL(v.x) ONL(v.y) ONL(v.z) ONL(v.w)
#undef ONL
    }
    __shared__ float sm[256], ss[256];
    sm[threadIdx.x] = m;
    ss[threadIdx.x] = s;
    __syncthreads();
    for (int off = 128; off; off >>= 1) {
        if (threadIdx.x < off) {
            float m1 = sm[threadIdx.x], s1 = ss[threadIdx.x];
            float m2 = sm[threadIdx.x + off], s2 = ss[threadIdx.x + off];
            float M = fmaxf(m1, m2);
            sm[threadIdx.x] = M;
            ss[threadIdx.x] = s1 * __expf(m1 - M) + s2 * __expf(m2 - M);
        }
        __syncthreads();
    }
    if (threadIdx.x == 0) {
        g_rowmax[b] = sm[0];
        g_rowinv[b] = 1.f / ss[0];
    }
}

// ---------------- out_probs = exp(G - max) * inv ----------------------------
__global__ void k_probs(float* __restrict__ out1) {
    int b  = blockIdx.y;
    int i4 = blockIdx.x * blockDim.x + threadIdx.x;
    if (i4 < VOUT / 4) {
        float m   = g_rowmax[b];
        float inv = g_rowinv[b];
        float4 g  = *((const float4*)(g_G + (size_t)b * VOUT) + i4);
        float4 o;
        o.x = __expf(g.x - m) * inv;
        o.y = __expf(g.y - m) * inv;
        o.z = __expf(g.z - m) * inv;
        o.w = __expf(g.w - m) * inv;
        *((float4*)(out1 + (size_t)b * VOUT) + i4) = o;
    }
}

// ---------------- launch ----------------------------------------------------
extern "C" void kernel_launch(void* const* d_in, const int* in_sizes, int n_in,
                              void* d_out, int out_size) {
    const float* x    = (const float*)d_in[0];
    const float* W    = (const float*)d_in[1];
    const float* bv   = (const float*)d_in[2];
    const float* attn = (const float*)d_in[3];
    const int*   ctx  = (const int*)d_in[4];
    const int*   i2a  = (const int*)d_in[5];
    const int*   omap = (const int*)d_in[6];
    const int*   mask = (const int*)d_in[7];

    float* out1 = (float*)d_out;                       // out_probs  [B, VOUT]
    float* out2 = out1 + (size_t)BSZ * VOUT;           // gen_masked [B, VOUT]

    k_sel_init <<<(VOUT + 255) / 256, 256>>>();
    k_sel_max  <<<(VINP + 255) / 256, 256>>>(i2a);
    k_win_build<<<(VINP + 255) / 256, 256>>>(i2a);

    k_perm_w<<<VOUT, 256>>>(W, bv, omap);

    dim3 ggrid((VOUT + 127) / 128, BSZ / 128);         // 391 x 8
    k_gemm<<<ggrid, 256>>>(x);

    dim3 egrid((VOUT / 4 + 255) / 256, BSZ);           // 49 x 1024
    k_masked<<<egrid, 256>>>(mask, out2);              // reads gen before scatter

    k_scatter<<<BSZ, SRCN>>>(attn, ctx);               // G becomes out_scores

    k_reduce<<<BSZ, 256>>>();
    k_probs <<<egrid, 256>>>(out1);
}

// round 3
// speedup vs baseline: 2.4432x; 2.4432x over previous
#include <cuda_runtime.h>
#include <cuda_bf16.h>
#include <cstdint>
#include <cstddef>

#define BSZ  1024
#define HD   1024
#define VOUT 50000
#define VINP 32000
#define SRCN 256

#define BM 128
#define BN 128
#define BK 32
#define NCH (HD / BK)            // 32 K-chunks

// smem tile layout: rows padded to 80B (40 bf16) -> conflict-free fragment LDS
#define ROWB 80
#define TILEB (128 * ROWB)       // 10240 B per tile
#define OFF_AH 0
#define OFF_AL (TILEB)
#define OFF_BH (2 * TILEB)
#define OFF_BL (3 * TILEB)
#define STAGE_BYTES (4 * TILEB)  // 40960
#define SMEM_TOTAL (2 * STAGE_BYTES)

// ---------------- scratch (static device globals) ---------------------------
__device__ __nv_bfloat16 g_Wh[(size_t)VOUT * HD];
__device__ __nv_bfloat16 g_Wl[(size_t)VOUT * HD];
__device__ __nv_bfloat16 g_Xh[(size_t)BSZ * HD];
__device__ __nv_bfloat16 g_Xl[(size_t)BSZ * HD];
__device__ float g_b2[VOUT];
__device__ float g_G [(size_t)BSZ * VOUT];          // gen_scores -> out_scores
__device__ int   g_sel[VOUT];
__device__ int   g_win[VINP];
__device__ float g_rowmax[BSZ];
__device__ float g_rowinv[BSZ];

// ---------------- PTX helpers ------------------------------------------------
__device__ __forceinline__ uint32_t smem_u32(const void* p) {
    uint32_t a;
    asm("{ .reg .u64 t; cvta.to.shared.u64 t, %1; cvt.u32.u64 %0, t; }"
        : "=r"(a) : "l"(p));
    return a;
}

__device__ __forceinline__ void cp16(uint32_t dst, const void* src, int nbytes) {
    asm volatile("cp.async.cg.shared.global [%0], [%1], 16, %2;"
                 :: "r"(dst), "l"(src), "r"(nbytes) : "memory");
}
#define CP_COMMIT() asm volatile("cp.async.commit_group;" ::: "memory")
#define CP_WAIT(n)  asm volatile("cp.async.wait_group %0;" :: "n"(n) : "memory")

__device__ __forceinline__ void mma_bf16(float* d, const uint32_t* a, const uint32_t* b) {
    asm volatile("mma.sync.aligned.m16n8k16.row.col.f32.bf16.bf16.f32 "
                 "{%0,%1,%2,%3}, {%4,%5,%6,%7}, {%8,%9}, {%0,%1,%2,%3};"
                 : "+f"(d[0]), "+f"(d[1]), "+f"(d[2]), "+f"(d[3])
                 : "r"(a[0]), "r"(a[1]), "r"(a[2]), "r"(a[3]),
                   "r"(b[0]), "r"(b[1]));
}

// ---------------- small prep kernels ----------------------------------------
__global__ void k_sel_init() {
    int i = blockIdx.x * 256 + threadIdx.x;
    if (i < VOUT) g_sel[i] = -1;
}
__global__ void k_sel_max(const int* __restrict__ i2a) {
    int i = blockIdx.x * 256 + threadIdx.x;
    if (i < VINP) atomicMax(&g_sel[i2a[i]], i);
}
__global__ void k_win_build(const int* __restrict__ i2a) {
    int i = blockIdx.x * 256 + threadIdx.x;
    if (i < VINP) {
        int a = i2a[i];
        g_win[i] = (g_sel[a] == i) ? a : -1;
    }
}

// permute W rows + split fp32 -> (bf16 hi, bf16 lo)
__global__ void k_prep_w(const float* __restrict__ W, const float* __restrict__ bias,
                         const int* __restrict__ omap) {
    int j  = blockIdx.x;
    int om = omap[j];
    float4 v = ((const float4*)(W + (size_t)om * HD))[threadIdx.x];
    size_t o = (size_t)j * HD + threadIdx.x * 4;
    float f[4] = {v.x, v.y, v.z, v.w};
    __nv_bfloat16 h[4], l[4];
#pragma unroll
    for (int i = 0; i < 4; ++i) {
        h[i] = __float2bfloat16_rn(f[i]);
        l[i] = __float2bfloat16_rn(f[i] - __bfloat162float(h[i]));
    }
    ((__nv_bfloat162*)(g_Wh + o))[0] = __nv_bfloat162(h[0], h[1]);
    ((__nv_bfloat162*)(g_Wh + o))[1] = __nv_bfloat162(h[2], h[3]);
    ((__nv_bfloat162*)(g_Wl + o))[0] = __nv_bfloat162(l[0], l[1]);
    ((__nv_bfloat162*)(g_Wl + o))[1] = __nv_bfloat162(l[2], l[3]);
    if (threadIdx.x == 0) g_b2[j] = bias[om];
}

__global__ void k_prep_x(const float* __restrict__ X) {
    int m = blockIdx.x;
    float4 v = ((const float4*)(X + (size_t)m * HD))[threadIdx.x];
    size_t o = (size_t)m * HD + threadIdx.x * 4;
    float f[4] = {v.x, v.y, v.z, v.w};
    __nv_bfloat16 h[4], l[4];
#pragma unroll
    for (int i = 0; i < 4; ++i) {
        h[i] = __float2bfloat16_rn(f[i]);
        l[i] = __float2bfloat16_rn(f[i] - __bfloat162float(h[i]));
    }
    ((__nv_bfloat162*)(g_Xh + o))[0] = __nv_bfloat162(h[0], h[1]);
    ((__nv_bfloat162*)(g_Xh + o))[1] = __nv_bfloat162(h[2], h[3]);
    ((__nv_bfloat162*)(g_Xl + o))[0] = __nv_bfloat162(l[0], l[1]);
    ((__nv_bfloat162*)(g_Xl + o))[1] = __nv_bfloat162(l[2], l[3]);
}

// ---------------- mma.sync GEMM ----------------------------------------------
__device__ __forceinline__ void issue_stage(uint32_t sb, int stage, int kc,
                                            int m0, int n0, int tid) {
    uint32_t base = sb + stage * STAGE_BYTES;
    for (int i = tid; i < 512; i += 256) {     // 128 rows * 4 16B-segments
        int r = i >> 2, s = i & 3;
        uint32_t doff = r * ROWB + s * 16;
        size_t asrc = (size_t)(m0 + r) * HD + kc * BK + s * 8;
        cp16(base + OFF_AH + doff, g_Xh + asrc, 16);
        cp16(base + OFF_AL + doff, g_Xl + asrc, 16);
        int nr = n0 + r;
        int p  = (nr < VOUT) ? 16 : 0;
        size_t bsrc = (size_t)(nr < VOUT ? nr : (VOUT - 1)) * HD + kc * BK + s * 8;
        cp16(base + OFF_BH + doff, g_Wh + bsrc, p);
        cp16(base + OFF_BL + doff, g_Wl + bsrc, p);
    }
}

__global__ __launch_bounds__(256, 1)
void k_gemm(const int* __restrict__ mask, float* __restrict__ out2) {
    extern __shared__ char smem[];
    uint32_t sb = smem_u32(smem);
    const int tid  = threadIdx.x;
    const int wid  = tid >> 5;
    const int lane = tid & 31;
    const int wm   = wid >> 1;          // 0..3 -> m
    const int wn   = wid & 1;           // 0..1 -> n
    const int m0   = blockIdx.x * BM;   // 8 m-tiles, fastest -> W reuse in L2
    const int n0   = blockIdx.y * BN;   // 391 n-tiles

    float acc[2][8][4];
#pragma unroll
    for (int i = 0; i < 2; ++i)
#pragma unroll
        for (int j = 0; j < 8; ++j)
#pragma unroll
            for (int q = 0; q < 4; ++q) acc[i][j][q] = 0.f;

    issue_stage(sb, 0, 0, m0, n0, tid);
    CP_COMMIT();

    const int lr = lane >> 2;          // 0..7
    const int lc = (lane & 3) * 2;     // 0,2,4,6

    for (int c = 0; c < NCH; ++c) {
        int s = c & 1;
        if (c + 1 < NCH) {
            issue_stage(sb, s ^ 1, c + 1, m0, n0, tid);
            CP_COMMIT();
            CP_WAIT(1);
        } else {
            CP_WAIT(0);
        }
        __syncthreads();

        const char* base = smem + s * STAGE_BYTES;
#pragma unroll
        for (int kk = 0; kk < 2; ++kk) {
            int k0 = kk * 16;
            uint32_t Ah[2][4], Al[2][4], Bh[8][2], Bl[8][2];
#pragma unroll
            for (int i = 0; i < 2; ++i) {
                int r = wm * 32 + i * 16 + lr;
                const char* pH = base + OFF_AH;
                const char* pL = base + OFF_AL;
                Ah[i][0] = *(const uint32_t*)(pH + (r    ) * ROWB + (k0 + lc    ) * 2);
                Ah[i][1] = *(const uint32_t*)(pH + (r + 8) * ROWB + (k0 + lc    ) * 2);
                Ah[i][2] = *(const uint32_t*)(pH + (r    ) * ROWB + (k0 + lc + 8) * 2);
                Ah[i][3] = *(const uint32_t*)(pH + (r + 8) * ROWB + (k0 + lc + 8) * 2);
                Al[i][0] = *(const uint32_t*)(pL + (r    ) * ROWB + (k0 + lc    ) * 2);
                Al[i][1] = *(const uint32_t*)(pL + (r + 8) * ROWB + (k0 + lc    ) * 2);
                Al[i][2] = *(const uint32_t*)(pL + (r    ) * ROWB + (k0 + lc + 8) * 2);
                Al[i][3] = *(const uint32_t*)(pL + (r + 8) * ROWB + (k0 + lc + 8) * 2);
            }
#pragma unroll
            for (int j = 0; j < 8; ++j) {
                int n = wn * 64 + j * 8 + lr;
                Bh[j][0] = *(const uint32_t*)(base + OFF_BH + n * ROWB + (k0 + lc    ) * 2);
                Bh[j][1] = *(const uint32_t*)(base + OFF_BH + n * ROWB + (k0 + lc + 8) * 2);
                Bl[j][0] = *(const uint32_t*)(base + OFF_BL + n * ROWB + (k0 + lc    ) * 2);
                Bl[j][1] = *(const uint32_t*)(base + OFF_BL + n * ROWB + (k0 + lc + 8) * 2);
            }
#pragma unroll
            for (int i = 0; i < 2; ++i)
#pragma unroll
                for (int j = 0; j < 8; ++j) mma_bf16(acc[i][j], Ah[i], Bh[j]);
#pragma unroll
            for (int i = 0; i < 2; ++i)
#pragma unroll
                for (int j = 0; j < 8; ++j) mma_bf16(acc[i][j], Ah[i], Bl[j]);
#pragma unroll
            for (int i = 0; i < 2; ++i)
#pragma unroll
                for (int j = 0; j < 8; ++j) mma_bf16(acc[i][j], Al[i], Bh[j]);
        }
        __syncthreads();
    }

    // epilogue: bias add, write G and gen_masked
#pragma unroll
    for (int i = 0; i < 2; ++i) {
        int r0 = m0 + wm * 32 + i * 16 + lr;
#pragma unroll
        for (int j = 0; j < 8; ++j) {
            int n = n0 + wn * 64 + j * 8 + lc;
            if (n < VOUT) {
                float2 bb = *(const float2*)(g_b2 + n);
                float gx = acc[i][j][0] + bb.x;
                float gy = acc[i][j][1] + bb.y;
                size_t o0 = (size_t)r0 * VOUT + n;
                *(float2*)(g_G + o0) = make_float2(gx, gy);
                int2 mk0 = *(const int2*)(mask + o0);
                *(float2*)(out2 + o0) =
                    make_float2(gx - 1.0e6f * (float)mk0.x, gy - 1.0e6f * (float)mk0.y);

                float gz = acc[i][j][2] + bb.x;
                float gw = acc[i][j][3] + bb.y;
                size_t o1 = (size_t)(r0 + 8) * VOUT + n;
                *(float2*)(g_G + o1) = make_float2(gz, gw);
                int2 mk1 = *(const int2*)(mask + o1);
                *(float2*)(out2 + o1) =
                    make_float2(gz - 1.0e6f * (float)mk1.x, gw - 1.0e6f * (float)mk1.y);
            }
        }
    }
}

// ---------------- scatter pointer scores into G -----------------------------
__global__ void k_scatter(const float* __restrict__ attn, const int* __restrict__ ctx) {
    int b = blockIdx.x;
    int j = threadIdx.x;
    int v = ctx[b * SRCN + j];
    int o = g_win[v];
    if (o >= 0) atomicAdd(g_G + (size_t)b * VOUT + o, attn[b * SRCN + j]);
}

// ---------------- online softmax reduce -------------------------------------
__global__ void k_reduce() {
    int b = blockIdx.x;
    const float4* Gr = (const float4*)(g_G + (size_t)b * VOUT);
    float m = -3.4e38f, s = 0.f;
    for (int i = threadIdx.x; i < VOUT / 4; i += blockDim.x) {
        float4 v = Gr[i];
#define ONL(x)                                                   \
        if ((x) > m) { s = s * __expf(m - (x)) + 1.f; m = (x); } \
        else         { s += __expf((x) - m); }
        ONL(v.x) ONL(v.y) ONL(v.z) ONL(v.w)
#undef ONL
    }
    __shared__ float sm[256], ss[256];
    sm[threadIdx.x] = m;
    ss[threadIdx.x] = s;
    __syncthreads();
    for (int off = 128; off; off >>= 1) {
        if (threadIdx.x < off) {
            float m1 = sm[threadIdx.x], s1 = ss[threadIdx.x];
            float m2 = sm[threadIdx.x + off], s2 = ss[threadIdx.x + off];
            float M = fmaxf(m1, m2);
            sm[threadIdx.x] = M;
            ss[threadIdx.x] = s1 * __expf(m1 - M) + s2 * __expf(m2 - M);
        }
        __syncthreads();
    }
    if (threadIdx.x == 0) {
        g_rowmax[b] = sm[0];
        g_rowinv[b] = 1.f / ss[0];
    }
}

__global__ void k_probs(float* __restrict__ out1) {
    int b  = blockIdx.y;
    int i4 = blockIdx.x * blockDim.x + threadIdx.x;
    if (i4 < VOUT / 4) {
        float m   = g_rowmax[b];
        float inv = g_rowinv[b];
        float4 g  = *((const float4*)(g_G + (size_t)b * VOUT) + i4);
        float4 o;
        o.x = __expf(g.x - m) * inv;
        o.y = __expf(g.y - m) * inv;
        o.z = __expf(g.z - m) * inv;
        o.w = __expf(g.w - m) * inv;
        *((float4*)(out1 + (size_t)b * VOUT) + i4) = o;
    }
}

// ---------------- launch ----------------------------------------------------
extern "C" void kernel_launch(void* const* d_in, const int* in_sizes, int n_in,
                              void* d_out, int out_size) {
    const float* x    = (const float*)d_in[0];
    const float* W    = (const float*)d_in[1];
    const float* bv   = (const float*)d_in[2];
    const float* attn = (const float*)d_in[3];
    const int*   ctx  = (const int*)d_in[4];
    const int*   i2a  = (const int*)d_in[5];
    const int*   omap = (const int*)d_in[6];
    const int*   mask = (const int*)d_in[7];

    float* out1 = (float*)d_out;                       // out_probs  [B, VOUT]
    float* out2 = out1 + (size_t)BSZ * VOUT;           // gen_masked [B, VOUT]

    cudaFuncSetAttribute(k_gemm, cudaFuncAttributeMaxDynamicSharedMemorySize, SMEM_TOTAL);

    k_sel_init <<<(VOUT + 255) / 256, 256>>>();
    k_sel_max  <<<(VINP + 255) / 256, 256>>>(i2a);
    k_win_build<<<(VINP + 255) / 256, 256>>>(i2a);

    k_prep_w<<<VOUT, 256>>>(W, bv, omap);
    k_prep_x<<<BSZ, 256>>>(x);

    dim3 ggrid(BSZ / BM, (VOUT + BN - 1) / BN);        // 8 x 391, m fastest
    k_gemm<<<ggrid, 256, SMEM_TOTAL>>>(mask, out2);    // writes G and gen_masked

    k_scatter<<<BSZ, SRCN>>>(attn, ctx);               // G becomes out_scores

    k_reduce<<<BSZ, 256>>>();
    dim3 egrid((VOUT / 4 + 255) / 256, BSZ);
    k_probs <<<egrid, 256>>>(out1);
}